// round 5
// baseline (speedup 1.0000x reference)
#include <cuda_runtime.h>
#include <cuda_fp16.h>
#include <cstdint>

// Problem dims (fixed)
#define O_DIM 2048
#define I_DIM 2048
#define M_DIM 4096
#define KC    256
#define PQD   8

// Scratch (device globals: allocation-free rule)
__device__ __align__(16) __half g_wq[O_DIM * I_DIM];  // quantized weight fp16 [O][I]
__device__ __align__(16) __half g_x [M_DIM * I_DIM];  // x fp16 [M][K]

// ===========================================================================
// helpers
// ===========================================================================
__device__ __forceinline__ uint64_t ffma2(uint64_t a, uint64_t b, uint64_t c) {
    uint64_t d;
    asm("fma.rn.f32x2 %0, %1, %2, %3;" : "=l"(d) : "l"(a), "l"(b), "l"(c));
    return d;
}
__device__ __forceinline__ uint64_t pack2(float lo, float hi) {
    uint64_t d; asm("mov.b64 %0, {%1, %2};" : "=l"(d) : "f"(lo), "f"(hi)); return d;
}
__device__ __forceinline__ void unpack2(uint64_t v, float& lo, float& hi) {
    asm("mov.b64 {%0, %1}, %2;" : "=f"(lo), "=f"(hi) : "l"(v));
}
__device__ __forceinline__ void cp_async16(uint32_t s, const void* g) {
    asm volatile("cp.async.cg.shared.global [%0], [%1], 16;" :: "r"(s), "l"(g) : "memory");
}

// ===========================================================================
// Kernel 1 (fused): blocks [0,512)   -> PQ quantize weight -> g_wq (fp16)
//                   blocks [512,4608)-> convert x fp32 -> g_x fp16
// ===========================================================================
#define QBLOCKS 512

__global__ __launch_bounds__(256) void prep_kernel(const float* __restrict__ x,
                                                   const float* __restrict__ w,
                                                   const float* __restrict__ cb,
                                                   const float* __restrict__ rs) {
    int tid = threadIdx.x;
    if (blockIdx.x >= QBLOCKS) {
        // ---- convert x ----
        size_t i = ((size_t)(blockIdx.x - QBLOCKS) * 256 + tid) * 8;
        float4 a = *reinterpret_cast<const float4*>(x + i);
        float4 b = *reinterpret_cast<const float4*>(x + i + 4);
        __half2 h0 = __floats2half2_rn(a.x, a.y);
        __half2 h1 = __floats2half2_rn(a.z, a.w);
        __half2 h2 = __floats2half2_rn(b.x, b.y);
        __half2 h3 = __floats2half2_rn(b.z, b.w);
        uint4 v;
        v.x = *reinterpret_cast<uint32_t*>(&h0);
        v.y = *reinterpret_cast<uint32_t*>(&h1);
        v.z = *reinterpret_cast<uint32_t*>(&h2);
        v.w = *reinterpret_cast<uint32_t*>(&h3);
        *reinterpret_cast<uint4*>(g_x + i) = v;
        return;
    }

    // ---- quantize: 4 groups per thread, packed f32x2 scoring ----
    // per codeword k: 8 pairs {c_j, c_j} + 1 pair {c2/2, c2/2}, stride 10 float2 (80B)
    __shared__ __align__(16) float2 scb2[KC][10];
    {
        const float4* cb4 = reinterpret_cast<const float4*>(cb);
        float4 a = cb4[tid * 2];
        float4 b = cb4[tid * 2 + 1];
        float s = a.x * a.x;
        s = fmaf(a.y, a.y, s); s = fmaf(a.z, a.z, s); s = fmaf(a.w, a.w, s);
        s = fmaf(b.x, b.x, s); s = fmaf(b.y, b.y, s); s = fmaf(b.z, b.z, s); s = fmaf(b.w, b.w, s);
        float c2h = 0.5f * s;
        scb2[tid][0] = make_float2(a.x, a.x);
        scb2[tid][1] = make_float2(a.y, a.y);
        scb2[tid][2] = make_float2(a.z, a.z);
        scb2[tid][3] = make_float2(a.w, a.w);
        scb2[tid][4] = make_float2(b.x, b.x);
        scb2[tid][5] = make_float2(b.y, b.y);
        scb2[tid][6] = make_float2(b.z, b.z);
        scb2[tid][7] = make_float2(b.w, b.w);
        scb2[tid][8] = make_float2(c2h, c2h);
    }
    __syncthreads();

    uint32_t scb_s = (uint32_t)__cvta_generic_to_shared(&scb2[0][0]);

    int t4 = blockIdx.x * 256 + tid;     // 0..131071
    int g0 = t4 * 4;                     // 4 groups, all within one weight row
    float scale = rs[g0 >> 8];           // 256 groups per row
    float inv = 1.0f / scale;

    float xv[32];
    {
        const float4* wp = reinterpret_cast<const float4*>(w + (size_t)g0 * PQD);
#pragma unroll
        for (int q = 0; q < 8; q++) {
            float4 v = wp[q];
            xv[q * 4 + 0] = v.x; xv[q * 4 + 1] = v.y;
            xv[q * 4 + 2] = v.z; xv[q * 4 + 3] = v.w;
        }
    }
    // negated, scaled, packed: P01[j] = {-x0j, -x1j}, P23[j] = {-x2j, -x3j}
    uint64_t P01[8], P23[8];
#pragma unroll
    for (int j = 0; j < 8; j++) {
        P01[j] = pack2(-(xv[j] * inv), -(xv[8 + j] * inv));
        P23[j] = pack2(-(xv[16 + j] * inv), -(xv[24 + j] * inv));
    }

    float b0 = 3.4e38f, b1 = 3.4e38f, b2 = 3.4e38f, b3 = 3.4e38f;
    int i0 = 0, i1 = 0, i2 = 0, i3 = 0;

#pragma unroll 4
    for (int k = 0; k < KC; k++) {
        uint32_t a = scb_s + (uint32_t)k * 80;
        uint64_t c0, c1, c2, c3, c4, c5, c6, c7, ch;
        asm("ld.shared.v2.u64 {%0,%1}, [%2];" : "=l"(c0), "=l"(c1) : "r"(a));
        asm("ld.shared.v2.u64 {%0,%1}, [%2];" : "=l"(c2), "=l"(c3) : "r"(a + 16));
        asm("ld.shared.v2.u64 {%0,%1}, [%2];" : "=l"(c4), "=l"(c5) : "r"(a + 32));
        asm("ld.shared.v2.u64 {%0,%1}, [%2];" : "=l"(c6), "=l"(c7) : "r"(a + 48));
        asm("ld.shared.b64 %0, [%1];" : "=l"(ch) : "r"(a + 64));
        uint64_t d01 = ch, d23 = ch;
        d01 = ffma2(P01[0], c0, d01); d23 = ffma2(P23[0], c0, d23);
        d01 = ffma2(P01[1], c1, d01); d23 = ffma2(P23[1], c1, d23);
        d01 = ffma2(P01[2], c2, d01); d23 = ffma2(P23[2], c2, d23);
        d01 = ffma2(P01[3], c3, d01); d23 = ffma2(P23[3], c3, d23);
        d01 = ffma2(P01[4], c4, d01); d23 = ffma2(P23[4], c4, d23);
        d01 = ffma2(P01[5], c5, d01); d23 = ffma2(P23[5], c5, d23);
        d01 = ffma2(P01[6], c6, d01); d23 = ffma2(P23[6], c6, d23);
        d01 = ffma2(P01[7], c7, d01); d23 = ffma2(P23[7], c7, d23);
        float s0, s1, s2, s3;
        unpack2(d01, s0, s1);
        unpack2(d23, s2, s3);
        if (s0 < b0) { b0 = s0; i0 = k; }
        if (s1 < b1) { b1 = s1; i1 = k; }
        if (s2 < b2) { b2 = s2; i2 = k; }
        if (s3 < b3) { b3 = s3; i3 = k; }
    }

    int idxs[4] = {i0, i1, i2, i3};
#pragma unroll
    for (int g = 0; g < 4; g++) {
        int bi = idxs[g];
        __half2 h[4];
#pragma unroll
        for (int j = 0; j < 4; j++) {
            float lo = scb2[bi][2 * j].x * scale;
            float hi = scb2[bi][2 * j + 1].x * scale;
            h[j] = __floats2half2_rn(lo, hi);
        }
        uint4 v;
        v.x = *reinterpret_cast<uint32_t*>(&h[0]);
        v.y = *reinterpret_cast<uint32_t*>(&h[1]);
        v.z = *reinterpret_cast<uint32_t*>(&h[2]);
        v.w = *reinterpret_cast<uint32_t*>(&h[3]);
        *reinterpret_cast<uint4*>(g_wq + (size_t)(g0 + g) * PQD) = v;
    }
}

// ===========================================================================
// Kernel 2: GEMM  out[M,N] = g_x[M,K] @ g_wq[N,K]^T + bias  (mma.sync fp16/f32)
//   128M x 256N x 32K block, 8 warps @ 64x64, 3-stage cp.async ring.
// ===========================================================================
#define GBM 128
#define GBN 256
#define GBK 32
#define LDSW 40                         // halves per smem row (32 + 8 pad)
#define A_BYTES (GBM * LDSW * 2)        // 10240
#define B_BYTES (GBN * LDSW * 2)        // 20480
#define STG_BYTES (A_BYTES + B_BYTES)   // 30720
#define NSTG 3
#define GSMEM (NSTG * STG_BYTES)        // 92160

__global__ __launch_bounds__(256, 1) void gemm_kernel(const float* __restrict__ bias,
                                                      float* __restrict__ out) {
    extern __shared__ char smem_raw[];
    uint32_t sb = (uint32_t)__cvta_generic_to_shared(smem_raw);

    int tid  = threadIdx.x;
    int lane = tid & 31;
    int wid  = tid >> 5;
    int bm0  = blockIdx.y * GBM;
    int bn0  = blockIdx.x * GBN;
    int wm   = (wid >> 2) * 64;      // 2 warps in M
    int wn   = (wid & 3) * 64;       // 4 warps in N

    // loader mapping: A: row=tid>>1, 2 chunks; B: row=tid, 4 chunks
    int arow = tid >> 1;
    int acol = (tid & 1) * 16;       // halves
    const __half* gAp = g_x  + (size_t)(bm0 + arow) * I_DIM + acol;
    const __half* gBp = g_wq + (size_t)(bn0 + tid) * I_DIM;
    uint32_t sa_off = (uint32_t)((arow * LDSW + acol) * 2);
    uint32_t sb_off = (uint32_t)(A_BYTES + tid * LDSW * 2);

#define G_LOAD(slot, k0)                                                     \
    do {                                                                     \
        uint32_t bse = sb + (uint32_t)(slot) * STG_BYTES;                    \
        cp_async16(bse + sa_off,      gAp + (k0));                           \
        cp_async16(bse + sa_off + 16, gAp + (k0) + 8);                       \
        cp_async16(bse + sb_off,      gBp + (k0));                           \
        cp_async16(bse + sb_off + 16, gBp + (k0) + 8);                       \
        cp_async16(bse + sb_off + 32, gBp + (k0) + 16);                      \
        cp_async16(bse + sb_off + 48, gBp + (k0) + 24);                      \
        asm volatile("cp.async.commit_group;" ::: "memory");                 \
    } while (0)

    float acc[4][8][4];
#pragma unroll
    for (int mi = 0; mi < 4; mi++)
#pragma unroll
        for (int ni = 0; ni < 8; ni++)
#pragma unroll
            for (int r = 0; r < 4; r++) acc[mi][ni][r] = 0.0f;

    // prologue: stages 0..1
    G_LOAD(0, 0);
    G_LOAD(1, GBK);

    uint32_t a_frag_off = (uint32_t)(((wm + (lane & 15)) * LDSW + (lane >> 4) * 8) * 2);
    uint32_t b_frag_off = (uint32_t)(A_BYTES +
        ((wn + (lane & 7) + ((lane >> 4) & 1) * 8) * LDSW + ((lane >> 3) & 1) * 8) * 2);

    const int KT = I_DIM / GBK;  // 64
    int slot = 0;     // slot of tile kt
    int wslot = 2;    // slot to write next prefetch into
    for (int kt = 0; kt < KT; kt++) {
        asm volatile("cp.async.wait_group 1;" ::: "memory");
        __syncthreads();
        if (kt + 2 < KT) {
            G_LOAD(wslot, (kt + 2) * GBK);
        } else {
            asm volatile("cp.async.commit_group;" ::: "memory");
        }

        uint32_t stg = sb + (uint32_t)slot * STG_BYTES;
        uint32_t aBase = stg + a_frag_off;
        uint32_t bBase = stg + b_frag_off;

#pragma unroll
        for (int ks = 0; ks < 2; ks++) {
            uint32_t a[4][4], b[8][2];
#pragma unroll
            for (int mi = 0; mi < 4; mi++) {
                uint32_t addr = aBase + (uint32_t)((mi * 16 * LDSW + ks * 16) * 2);
                asm volatile("ldmatrix.sync.aligned.m8n8.x4.shared.b16 {%0,%1,%2,%3}, [%4];"
                             : "=r"(a[mi][0]), "=r"(a[mi][1]), "=r"(a[mi][2]), "=r"(a[mi][3])
                             : "r"(addr));
            }
#pragma unroll
            for (int p = 0; p < 4; p++) {
                uint32_t addr = bBase + (uint32_t)((p * 16 * LDSW + ks * 16) * 2);
                asm volatile("ldmatrix.sync.aligned.m8n8.x4.shared.b16 {%0,%1,%2,%3}, [%4];"
                             : "=r"(b[2 * p][0]), "=r"(b[2 * p][1]),
                               "=r"(b[2 * p + 1][0]), "=r"(b[2 * p + 1][1])
                             : "r"(addr));
            }
#pragma unroll
            for (int mi = 0; mi < 4; mi++)
#pragma unroll
                for (int ni = 0; ni < 8; ni++) {
                    asm volatile(
                        "mma.sync.aligned.m16n8k16.row.col.f32.f16.f16.f32 "
                        "{%0,%1,%2,%3}, {%4,%5,%6,%7}, {%8,%9}, {%0,%1,%2,%3};"
                        : "+f"(acc[mi][ni][0]), "+f"(acc[mi][ni][1]),
                          "+f"(acc[mi][ni][2]), "+f"(acc[mi][ni][3])
                        : "r"(a[mi][0]), "r"(a[mi][1]), "r"(a[mi][2]), "r"(a[mi][3]),
                          "r"(b[ni][0]), "r"(b[ni][1]));
                }
        }
        slot  = (slot == 2)  ? 0 : slot + 1;
        wslot = (wslot == 2) ? 0 : wslot + 1;
    }

    // epilogue: += bias, fp32 store
#pragma unroll
    for (int mi = 0; mi < 4; mi++) {
        int row = bm0 + wm + mi * 16 + (lane >> 2);
        float* o0 = out + (size_t)row * O_DIM;
        float* o1 = out + (size_t)(row + 8) * O_DIM;
#pragma unroll
        for (int ni = 0; ni < 8; ni++) {
            int col = bn0 + wn + ni * 8 + (lane & 3) * 2;
            float bv0 = bias[col];
            float bv1 = bias[col + 1];
            *reinterpret_cast<float2*>(o0 + col) =
                make_float2(acc[mi][ni][0] + bv0, acc[mi][ni][1] + bv1);
            *reinterpret_cast<float2*>(o1 + col) =
                make_float2(acc[mi][ni][2] + bv0, acc[mi][ni][3] + bv1);
        }
    }
}

// ===========================================================================
extern "C" void kernel_launch(void* const* d_in, const int* in_sizes, int n_in,
                              void* d_out, int out_size) {
    const float* x    = (const float*)d_in[0];
    const float* w    = (const float*)d_in[1];
    const float* cb   = (const float*)d_in[2];
    const float* rs   = (const float*)d_in[3];
    const float* bias = (const float*)d_in[4];
    float* out = (float*)d_out;

    static bool attr_done = false;
    if (!attr_done) {
        cudaFuncSetAttribute(gemm_kernel, cudaFuncAttributeMaxDynamicSharedMemorySize, GSMEM);
        attr_done = true;
    }

    prep_kernel<<<QBLOCKS + M_DIM * I_DIM / (256 * 8), 256>>>(x, w, cb, rs);
    dim3 grid(O_DIM / GBN, M_DIM / GBM);
    gemm_kernel<<<grid, 256, GSMEM>>>(bias, out);
}